// round 13
// baseline (speedup 1.0000x reference)
#include <cuda_runtime.h>
#include <cooperative_groups.h>

namespace cg = cooperative_groups;

#define N_QUBITS 15
#define N_LAYERS 4
#define BATCHN   64
#define NLOC     16384            // per-CTA amplitudes (2^14)
#define NTHREADS 1024
#define SMEM_BYTES (NLOC * sizeof(float2))   // 131072 B

// Exchange buffers: [batch][slot(2)][rank(2)][NLOC]  (double-buffered).
__device__ float2 g_xchg[BATCHN * 2 * 2 * NLOC];

// ---------------------------------------------------------------------------
// Factored rotation on register bit BIT of a 16-amp subcube.
// tf = type*2 + form: type 0=RX 1=RY 2=RZ; form 0: t=s/c, form 1: u=c/s.
// ---------------------------------------------------------------------------
template<int BIT>
__device__ __forceinline__ void rotfac16(float2* a, float t, int tf) {
  if (tf == 0) {          // RX /c
#pragma unroll
    for (int j = 0; j < 16; j++) if (((j >> BIT) & 1) == 0) {
      const int k = j | (1 << BIT);
      float2 A0 = a[j], A1 = a[k];
      a[j].x = fmaf( t, A1.y, A0.x);  a[j].y = fmaf(-t, A1.x, A0.y);
      a[k].x = fmaf( t, A0.y, A1.x);  a[k].y = fmaf(-t, A0.x, A1.y);
    }
  } else if (tf == 1) {   // RX /s
#pragma unroll
    for (int j = 0; j < 16; j++) if (((j >> BIT) & 1) == 0) {
      const int k = j | (1 << BIT);
      float2 A0 = a[j], A1 = a[k];
      a[j].x = fmaf(t, A0.x,  A1.y);  a[j].y = fmaf(t, A0.y, -A1.x);
      a[k].x = fmaf(t, A1.x,  A0.y);  a[k].y = fmaf(t, A1.y, -A0.x);
    }
  } else if (tf == 2) {   // RY /c
#pragma unroll
    for (int j = 0; j < 16; j++) if (((j >> BIT) & 1) == 0) {
      const int k = j | (1 << BIT);
      float2 A0 = a[j], A1 = a[k];
      a[j].x = fmaf(-t, A1.x, A0.x);  a[j].y = fmaf(-t, A1.y, A0.y);
      a[k].x = fmaf( t, A0.x, A1.x);  a[k].y = fmaf( t, A0.y, A1.y);
    }
  } else if (tf == 3) {   // RY /s
#pragma unroll
    for (int j = 0; j < 16; j++) if (((j >> BIT) & 1) == 0) {
      const int k = j | (1 << BIT);
      float2 A0 = a[j], A1 = a[k];
      a[j].x = fmaf(t, A0.x, -A1.x);  a[j].y = fmaf(t, A0.y, -A1.y);
      a[k].x = fmaf(t, A1.x,  A0.x);  a[k].y = fmaf(t, A1.y,  A0.y);
    }
  } else if (tf == 4) {   // RZ /c
#pragma unroll
    for (int j = 0; j < 16; j++) if (((j >> BIT) & 1) == 0) {
      const int k = j | (1 << BIT);
      float2 A0 = a[j], A1 = a[k];
      a[j].x = fmaf( t, A0.y, A0.x);  a[j].y = fmaf(-t, A0.x, A0.y);
      a[k].x = fmaf(-t, A1.y, A1.x);  a[k].y = fmaf( t, A1.x, A1.y);
    }
  } else {                // RZ /s
#pragma unroll
    for (int j = 0; j < 16; j++) if (((j >> BIT) & 1) == 0) {
      const int k = j | (1 << BIT);
      float2 A0 = a[j], A1 = a[k];
      a[j].x = fmaf(t, A0.x,  A0.y);  a[j].y = fmaf(t, A0.y, -A0.x);
      a[k].x = fmaf(t, A1.x, -A1.y);  a[k].y = fmaf(t, A1.y,  A1.x);
    }
  }
}

// Factored rotation on a lane-bit qubit (amp bit = lane bit LB), 16 regs.
template<int LB>
__device__ __forceinline__ void rot_lane_fac16(float2* a, float t, int tf, int lane) {
  const int cb = (lane >> LB) & 1;
  if (tf == 0) {          // RX /c
#pragma unroll
    for (int j = 0; j < 16; j++) {
      float px = __shfl_xor_sync(0xffffffffu, a[j].x, 1 << LB);
      float py = __shfl_xor_sync(0xffffffffu, a[j].y, 1 << LB);
      float nx = fmaf( t, py, a[j].x);
      float ny = fmaf(-t, px, a[j].y);
      a[j].x = nx; a[j].y = ny;
    }
  } else if (tf == 1) {   // RX /s
#pragma unroll
    for (int j = 0; j < 16; j++) {
      float px = __shfl_xor_sync(0xffffffffu, a[j].x, 1 << LB);
      float py = __shfl_xor_sync(0xffffffffu, a[j].y, 1 << LB);
      a[j].x = fmaf(t, a[j].x,  py);
      a[j].y = fmaf(t, a[j].y, -px);
    }
  } else if (tf == 2) {   // RY /c
    const float sg = cb ? t : -t;
#pragma unroll
    for (int j = 0; j < 16; j++) {
      float px = __shfl_xor_sync(0xffffffffu, a[j].x, 1 << LB);
      float py = __shfl_xor_sync(0xffffffffu, a[j].y, 1 << LB);
      a[j].x = fmaf(sg, px, a[j].x);
      a[j].y = fmaf(sg, py, a[j].y);
    }
  } else if (tf == 3) {   // RY /s
#pragma unroll
    for (int j = 0; j < 16; j++) {
      float px = __shfl_xor_sync(0xffffffffu, a[j].x, 1 << LB);
      float py = __shfl_xor_sync(0xffffffffu, a[j].y, 1 << LB);
      a[j].x = fmaf(t, a[j].x, cb ? px : -px);
      a[j].y = fmaf(t, a[j].y, cb ? py : -py);
    }
  } else if (tf == 4) {   // RZ /c: diagonal, no shfl
    const float tt = cb ? -t : t;
#pragma unroll
    for (int j = 0; j < 16; j++) {
      float nx = fmaf( tt, a[j].y, a[j].x);
      float ny = fmaf(-tt, a[j].x, a[j].y);
      a[j].x = nx; a[j].y = ny;
    }
  } else {                // RZ /s: diagonal, no shfl
#pragma unroll
    for (int j = 0; j < 16; j++) {
      float nx = fmaf(t, a[j].x, cb ? -a[j].y : a[j].y);
      float ny = fmaf(t, a[j].y, cb ?  a[j].x : -a[j].x);
      a[j].x = nx; a[j].y = ny;
    }
  }
}

template<int BC, int BT>
__device__ __forceinline__ void cnotl16(float2* a) {
#pragma unroll
  for (int j = 0; j < 16; j++) {
    if (((j >> BC) & 1) == 1 && ((j >> BT) & 1) == 0) {
      int k = j | (1 << BT);
      float2 t = a[j]; a[j] = a[k]; a[k] = t;
    }
  }
}

template<int BT>
__device__ __forceinline__ void xcond16(float2* a, bool c) {
#pragma unroll
  for (int j = 0; j < 16; j++) {
    if (((j >> BT) & 1) == 0) {
      int k = j | (1 << BT);
      float2 t0 = a[j], t1 = a[k];
      a[j] = c ? t1 : t0;
      a[k] = c ? t0 : t1;
    }
  }
}

// Generic factored pair rotation: m = value with qubit label lbl, o = partner
// (label lbl^1); returns new value at label lbl.
__device__ __forceinline__ float2 rotp(float2 m, float2 o, float t,
                                       int f, int lbl) {
  float2 r;
  if (f == 0) {        // RX /c
    r.x = fmaf( t, o.y, m.x);  r.y = fmaf(-t, o.x, m.y);
  } else if (f == 1) { // RX /s
    r.x = fmaf(t, m.x,  o.y);  r.y = fmaf(t, m.y, -o.x);
  } else if (f == 2) { // RY /c
    float sg = lbl ? t : -t;
    r.x = fmaf(sg, o.x, m.x);  r.y = fmaf(sg, o.y, m.y);
  } else {             // RY /s
    r.x = fmaf(t, m.x, lbl ? o.x : -o.x);
    r.y = fmaf(t, m.y, lbl ? o.y : -o.y);
  }
  return r;
}

__device__ __forceinline__ float2 rotd(float2 m, float t, int f, int lbl) {
  float2 r;
  if (f == 4) {        // RZ /c
    float tt = lbl ? -t : t;
    r.x = fmaf( tt, m.y, m.x);  r.y = fmaf(-tt, m.x, m.y);
  } else {             // RZ /s
    r.x = fmaf(t, m.x, lbl ? -m.y : m.y);
    r.y = fmaf(t, m.y, lbl ?  m.x : -m.x);
  }
  return r;
}

// Local amp index i: 14 bits; local bit k <-> qubit (14 - k) (qubits 1..14).
// Qubit 0 <-> cluster rank. Class = (q0 label, q1).
__global__ void __launch_bounds__(NTHREADS, 1) __cluster_dims__(2, 1, 1)
qdarts_kernel(const float* __restrict__ x, const float* __restrict__ Pm,
              const float* __restrict__ Qm, const float* __restrict__ rotp_,
              const float* __restrict__ gum, float* __restrict__ out)
{
  extern __shared__ float2 SM[];   // NLOC float2, LINEAR layout

  __shared__ float st_t[N_LAYERS * N_QUBITS];
  __shared__ int   st_f[N_LAYERS * N_QUBITS];
  __shared__ float st_s[N_LAYERS * N_QUBITS];
  __shared__ float sw[N_QUBITS][2];
  __shared__ float sred[4];
  __shared__ float sS2;

  cg::cluster_group cluster = cg::this_cluster();
  const int tid  = threadIdx.x;
  const int b    = blockIdx.x >> 1;
  const int rank = blockIdx.x & 1;
  const int lane = tid & 31;

  // ---- Gate selection: argmax(P@Q + gumbel); store (t, variant, scale). ----
  if (tid < N_LAYERS * N_QUBITS) {
    const int ix = tid;
    float best = -1e30f; int gb = 0;
#pragma unroll
    for (int gg = 0; gg < 3; gg++) {
      float logit = 0.f;
#pragma unroll
      for (int k = 0; k < 4; k++)
        logit += Pm[ix * 4 + k] * Qm[(ix * 4 + k) * 3 + gg];
      float v = logit + gum[ix * 3 + gg];
      if (v > best) { best = v; gb = gg; }
    }
    float sv, cv;
    sincosf(0.5f * rotp_[ix], &sv, &cv);
    const bool formB = fabsf(sv) > fabsf(cv);
    st_f[ix] = gb * 2 + (formB ? 1 : 0);
    st_t[ix] = formB ? __fdividef(cv, sv) : __fdividef(sv, cv);
    st_s[ix] = formB ? sv : cv;
  }
  if (tid < N_QUBITS) {
    float sv, cv;
    sincosf(0.5f * x[b * N_QUBITS + tid], &sv, &cv);
    sw[tid][0] = cv; sw[tid][1] = sv;
  }
  if (tid < 4) sred[tid] = 0.f;
  __syncthreads();

  if (tid == 0) {
    float pr = 1.f;
#pragma unroll 1
    for (int i = 0; i < N_LAYERS * N_QUBITS; i++) pr *= st_s[i];
    sS2 = pr * pr;
  }

  // Forward (dst) lane permutation for CNOT chain (10,11)..(13,14):
  // d4=b4; d3=b3^d4; d2=b2^d3; d1=b1^d2; d0=b0^d1 (cascade, updated bits).
  // CNOT(9,10) (ctrl = reg bit0) pre-flips b4 -> Chain(L^16) = Chain(L)^31.
  int u_ = lane;
  u_ ^= (u_ >> 1) & 8;
  u_ ^= (u_ >> 1) & 4;
  u_ ^= (u_ >> 1) & 2;
  u_ ^= (u_ >> 1) & 1;
  const int dstE = u_;
  const int dstO = u_ ^ 31;

  float pA = 0.f, pB = 0.f;
  const int  tb9 = (tid >> 9) & 1;    // q5 (sweep A) / q1 (sweep B) helper bit
  const bool odd = (tid & 1) != 0;    // q14 (amp bit0) — CNOT(14,0) control

#pragma unroll 1
  for (int l = 0; l < N_LAYERS; l++) {
    const int g0 = l * N_QUBITS;
    float2 a[16];

    // ======== Sweep A: amp = (j<<10)|tid; reg j = amp bits 13..10 (q1..q4) ====
    // R_q0 and R_q5 applied as pair-on-load; CNOT(14,0) of layer l-1 fused.
    {
      const float t0 = st_t[g0];     const int f0 = st_f[g0];
      const float t5 = st_t[g0 + 5]; const int f5 = st_f[g0 + 5];
      const bool q0d = (f0 >= 4), q5d = (f5 >= 4);

      if (l == 0) {
        float pref = 1.f;
#pragma unroll
        for (int q = 6; q < 15; q++) pref *= sw[q][(tid >> (14 - q)) & 1];
        const float w5m = sw[5][tb9], w5o = sw[5][tb9 ^ 1];
        const float w0m = sw[0][rank], w0o = sw[0][rank ^ 1];
#pragma unroll
        for (int j = 0; j < 16; j++) {
          float f = pref;
#pragma unroll
          for (int q = 1; q < 5; q++) f *= sw[q][(j >> (4 - q)) & 1];
          float2 mv, ov;
          if (q5d) {
            mv = rotd(make_float2(f * w5m * w0m, 0.f), t5, f5, tb9);
            ov = rotd(make_float2(f * w5m * w0o, 0.f), t5, f5, tb9);
          } else {
            mv = rotp(make_float2(f * w5m * w0m, 0.f),
                      make_float2(f * w5o * w0m, 0.f), t5, f5, tb9);
            ov = rotp(make_float2(f * w5m * w0o, 0.f),
                      make_float2(f * w5o * w0o, 0.f), t5, f5, tb9);
          }
          a[j] = q0d ? rotd(mv, t0, f0, rank) : rotp(mv, ov, t0, f0, rank);
        }
      } else {
        const float2* pg = g_xchg + ((size_t)(b * 2 + ((l - 1) & 1)) * 2
                                     + (rank ^ 1)) * NLOC;
        if (q0d) {          // R_q0 diagonal: only the post-CNOT own chain.
          if (q5d) {
#pragma unroll
            for (int j = 0; j < 16; j++) {
              const int i = (j << 10) | tid;
              a[j] = odd ? __ldcg(&pg[i]) : SM[i];
            }
#pragma unroll
            for (int j = 0; j < 16; j++)
              a[j] = rotd(rotd(a[j], t5, f5, tb9), t0, f0, rank);
          } else {
#pragma unroll
            for (int j = 0; j < 16; j++) {
              const int i = (j << 10) | tid, i2 = i ^ 512;
              float2 v  = odd ? __ldcg(&pg[i])  : SM[i];
              float2 v2 = odd ? __ldcg(&pg[i2]) : SM[i2];
              a[j] = rotd(rotp(v, v2, t5, f5, tb9), t0, f0, rank);
            }
          }
        } else {
          if (q5d) {
            // Batch partner loads first (L2 latency overlap, MLP=16).
#pragma unroll
            for (int j = 0; j < 16; j++)
              a[j] = __ldcg(&pg[(j << 10) | tid]);
#pragma unroll
            for (int j = 0; j < 16; j++) {
              const int i = (j << 10) | tid;
              float2 sA = SM[i];
              float2 mv = rotd(odd ? a[j] : sA, t5, f5, tb9);
              float2 ov = rotd(odd ? sA : a[j], t5, f5, tb9);
              a[j] = rotp(mv, ov, t0, f0, rank);
            }
          } else {
#pragma unroll
            for (int j = 0; j < 16; j++)
              a[j] = __ldcg(&pg[(j << 10) | tid]);
#pragma unroll
            for (int j = 0; j < 16; j++) {
              const int i = (j << 10) | tid, i2 = i ^ 512;
              float2 gB = __ldcg(&pg[i2]);
              float2 sA = SM[i], sB = SM[i2];
              float2 mv = rotp(odd ? a[j] : sA, odd ? gB : sB, t5, f5, tb9);
              float2 ov = rotp(odd ? sA : a[j], odd ? sB : gB, t5, f5, tb9);
              a[j] = rotp(mv, ov, t0, f0, rank);
            }
          }
        }
      }
      rotfac16<3>(a, st_t[g0 + 1], st_f[g0 + 1]);  // R_q1
      rotfac16<2>(a, st_t[g0 + 2], st_f[g0 + 2]);  // R_q2
      rotfac16<1>(a, st_t[g0 + 3], st_f[g0 + 3]);  // R_q3
      rotfac16<0>(a, st_t[g0 + 4], st_f[g0 + 4]);  // R_q4
      // CNOT(0,1): ctrl q0 = rank (uniform) -> swap reg bit3.
      if (rank) {
#pragma unroll
        for (int j = 0; j < 8; j++) {
          float2 t2 = a[j]; a[j] = a[j | 8]; a[j | 8] = t2;
        }
      }
      cnotl16<3, 2>(a);  // CNOT(1,2)
      cnotl16<2, 1>(a);  // CNOT(2,3)
      cnotl16<1, 0>(a);  // CNOT(3,4)
      // CNOT(4,5): ctrl q4 = reg bit0, tgt q5 = amp bit9 -> store transform.
#pragma unroll
      for (int j = 0; j < 16; j++)
        SM[((j << 10) | tid) ^ ((j & 1) << 9)] = a[j];
    }
    __syncthreads();

    // ======== Sweep B: amp = (w5<<9)|(jb<<5)|lane ========
    // reg jb = amp bits 8..5 (q6..q9); lane = amp bits 4..0 (q10..q14).
    {
      const int w5 = tid >> 5;
      const int base = (w5 << 9) | lane;
#pragma unroll
      for (int j = 0; j < 16; j++) a[j] = SM[base | (j << 5)];
      // Rotations q6..q9 (register bits 3..0)
      rotfac16<3>(a, st_t[g0 + 6], st_f[g0 + 6]);
      rotfac16<2>(a, st_t[g0 + 7], st_f[g0 + 7]);
      rotfac16<1>(a, st_t[g0 + 8], st_f[g0 + 8]);
      rotfac16<0>(a, st_t[g0 + 9], st_f[g0 + 9]);
      // Rotations q10..q14 (lane bits 4..0)
      rot_lane_fac16<4>(a, st_t[g0 + 10], st_f[g0 + 10], lane);
      rot_lane_fac16<3>(a, st_t[g0 + 11], st_f[g0 + 11], lane);
      rot_lane_fac16<2>(a, st_t[g0 + 12], st_f[g0 + 12], lane);
      rot_lane_fac16<1>(a, st_t[g0 + 13], st_f[g0 + 13], lane);
      rot_lane_fac16<0>(a, st_t[g0 + 14], st_f[g0 + 14], lane);
      // CNOT(5,6): ctrl q5 = amp bit9 = w5 bit0; tgt q6 = reg bit3.
      xcond16<3>(a, (w5 & 1) != 0);
      cnotl16<3, 2>(a);  // CNOT(6,7)
      cnotl16<2, 1>(a);  // CNOT(7,8)
      cnotl16<1, 0>(a);  // CNOT(8,9)
      // CNOT(9,10)+(10,11)+(11,12)+(12,13)+(13,14): folded into the STORE
      // ADDRESS as a lane permutation (dstE for even j, dstO = dstE^31 for
      // odd j). Bijective per 32-slot row -> conflict-free STS, coalesced STG.
      // CNOT(14,0): physical, fused into next layer's sweep-A loads
      // (or into the class remap below for the last layer).

      if (l < N_LAYERS - 1) {
        float2* xw = g_xchg + ((size_t)(b * 2 + (l & 1)) * 2 + rank) * NLOC;
        const int baseE = (w5 << 9) | dstE;
        const int baseO = (w5 << 9) | dstO;
#pragma unroll
        for (int j = 0; j < 16; j++) {
          const int i = ((j & 1) ? baseO : baseE) | (j << 5);
          SM[i] = a[j];
          xw[i] = a[j];
        }
        cluster.sync();
      } else {
        // |amp|^2 class reduction with the perm + CNOT(14,0) fold.
        // Final q14 of even-j amps = dstE&1, of odd-j amps = dstE&1 ^ 1.
        // class = (q0 label, q1); q1 = amp bit13 = tid bit9; q0 label flips
        // (rank -> rank^1) when q14 = 1.
        float pe = 0.f, po = 0.f;
#pragma unroll
        for (int j = 0; j < 16; j++) {
          float p = fmaf(a[j].x, a[j].x, a[j].y * a[j].y);
          if (j & 1) po += p; else pe += p;
        }
        const int e0 = dstE & 1;
        pA = e0 ? po : pe;   // q14 = 0 -> q0 label = rank
        pB = e0 ? pe : po;   // q14 = 1 -> q0 label = rank^1
      }
    }
  }

  // ---- Reduce: full warp reduce (classes warp-uniform) -> shared -> CTA ----
#pragma unroll
  for (int o = 16; o > 0; o >>= 1) {
    pA += __shfl_xor_sync(0xffffffffu, pA, o);
    pB += __shfl_xor_sync(0xffffffffu, pB, o);
  }
  if (lane == 0) {
    atomicAdd(&sred[(rank << 1) | tb9], pA);
    atomicAdd(&sred[((rank ^ 1) << 1) | tb9], pB);
  }
  __syncthreads();

  if (rank == 1 && tid < 4) {
    float* dst = cluster.map_shared_rank(sred, 0);
    atomicAdd(dst + tid, sred[tid]);
  }
  cluster.sync();
  if (rank == 0 && tid < 4) out[b * 4 + tid] = sred[tid] * sS2;
}

extern "C" void kernel_launch(void* const* d_in, const int* in_sizes, int n_in,
                              void* d_out, int out_size) {
  const float* x    = (const float*)d_in[0];
  const float* P    = (const float*)d_in[1];
  const float* Q    = (const float*)d_in[2];
  const float* rotp = (const float*)d_in[3];
  const float* gum  = (const float*)d_in[4];
  cudaFuncSetAttribute(qdarts_kernel,
                       cudaFuncAttributeMaxDynamicSharedMemorySize,
                       (int)SMEM_BYTES);
  qdarts_kernel<<<BATCHN * 2, NTHREADS, SMEM_BYTES>>>(x, P, Q, rotp, gum,
                                                      (float*)d_out);
}

// round 15
// speedup vs baseline: 1.1290x; 1.1290x over previous
#include <cuda_runtime.h>
#include <cooperative_groups.h>

namespace cg = cooperative_groups;

#define N_QUBITS 15
#define N_LAYERS 4
#define BATCHN   64
#define NLOC     16384            // per-CTA amplitudes (2^14)
#define NTHREADS 1024
#define SMEM_BYTES (NLOC * sizeof(float2))   // 131072 B

// Exchange buffers: [batch][slot(2)][rank(2)][NLOC] float2, as float4 pairs
// (16B alignment for vector loads).
__device__ float4 g_xchg4[BATCHN * 2 * 2 * NLOC / 2];

// ---------------------------------------------------------------------------
// Factored rotation on register bit BIT of a 16-amp subcube.
// tf = type*2 + form: type 0=RX 1=RY 2=RZ; form 0: t=s/c, form 1: u=c/s.
// ---------------------------------------------------------------------------
template<int BIT>
__device__ __forceinline__ void rotfac16(float2* a, float t, int tf) {
  if (tf == 0) {          // RX /c
#pragma unroll
    for (int j = 0; j < 16; j++) if (((j >> BIT) & 1) == 0) {
      const int k = j | (1 << BIT);
      float2 A0 = a[j], A1 = a[k];
      a[j].x = fmaf( t, A1.y, A0.x);  a[j].y = fmaf(-t, A1.x, A0.y);
      a[k].x = fmaf( t, A0.y, A1.x);  a[k].y = fmaf(-t, A0.x, A1.y);
    }
  } else if (tf == 1) {   // RX /s
#pragma unroll
    for (int j = 0; j < 16; j++) if (((j >> BIT) & 1) == 0) {
      const int k = j | (1 << BIT);
      float2 A0 = a[j], A1 = a[k];
      a[j].x = fmaf(t, A0.x,  A1.y);  a[j].y = fmaf(t, A0.y, -A1.x);
      a[k].x = fmaf(t, A1.x,  A0.y);  a[k].y = fmaf(t, A1.y, -A0.x);
    }
  } else if (tf == 2) {   // RY /c
#pragma unroll
    for (int j = 0; j < 16; j++) if (((j >> BIT) & 1) == 0) {
      const int k = j | (1 << BIT);
      float2 A0 = a[j], A1 = a[k];
      a[j].x = fmaf(-t, A1.x, A0.x);  a[j].y = fmaf(-t, A1.y, A0.y);
      a[k].x = fmaf( t, A0.x, A1.x);  a[k].y = fmaf( t, A0.y, A1.y);
    }
  } else if (tf == 3) {   // RY /s
#pragma unroll
    for (int j = 0; j < 16; j++) if (((j >> BIT) & 1) == 0) {
      const int k = j | (1 << BIT);
      float2 A0 = a[j], A1 = a[k];
      a[j].x = fmaf(t, A0.x, -A1.x);  a[j].y = fmaf(t, A0.y, -A1.y);
      a[k].x = fmaf(t, A1.x,  A0.x);  a[k].y = fmaf(t, A1.y,  A0.y);
    }
  } else if (tf == 4) {   // RZ /c
#pragma unroll
    for (int j = 0; j < 16; j++) if (((j >> BIT) & 1) == 0) {
      const int k = j | (1 << BIT);
      float2 A0 = a[j], A1 = a[k];
      a[j].x = fmaf( t, A0.y, A0.x);  a[j].y = fmaf(-t, A0.x, A0.y);
      a[k].x = fmaf(-t, A1.y, A1.x);  a[k].y = fmaf( t, A1.x, A1.y);
    }
  } else {                // RZ /s
#pragma unroll
    for (int j = 0; j < 16; j++) if (((j >> BIT) & 1) == 0) {
      const int k = j | (1 << BIT);
      float2 A0 = a[j], A1 = a[k];
      a[j].x = fmaf(t, A0.x,  A0.y);  a[j].y = fmaf(t, A0.y, -A0.x);
      a[k].x = fmaf(t, A1.x, -A1.y);  a[k].y = fmaf(t, A1.y,  A1.x);
    }
  }
}

// Factored rotation on a lane-bit qubit (amp bit = lane bit LB), 16 regs.
template<int LB>
__device__ __forceinline__ void rot_lane_fac16(float2* a, float t, int tf, int lane) {
  const int cb = (lane >> LB) & 1;
  if (tf == 0) {          // RX /c
#pragma unroll
    for (int j = 0; j < 16; j++) {
      float px = __shfl_xor_sync(0xffffffffu, a[j].x, 1 << LB);
      float py = __shfl_xor_sync(0xffffffffu, a[j].y, 1 << LB);
      float nx = fmaf( t, py, a[j].x);
      float ny = fmaf(-t, px, a[j].y);
      a[j].x = nx; a[j].y = ny;
    }
  } else if (tf == 1) {   // RX /s
#pragma unroll
    for (int j = 0; j < 16; j++) {
      float px = __shfl_xor_sync(0xffffffffu, a[j].x, 1 << LB);
      float py = __shfl_xor_sync(0xffffffffu, a[j].y, 1 << LB);
      a[j].x = fmaf(t, a[j].x,  py);
      a[j].y = fmaf(t, a[j].y, -px);
    }
  } else if (tf == 2) {   // RY /c
    const float sg = cb ? t : -t;
#pragma unroll
    for (int j = 0; j < 16; j++) {
      float px = __shfl_xor_sync(0xffffffffu, a[j].x, 1 << LB);
      float py = __shfl_xor_sync(0xffffffffu, a[j].y, 1 << LB);
      a[j].x = fmaf(sg, px, a[j].x);
      a[j].y = fmaf(sg, py, a[j].y);
    }
  } else if (tf == 3) {   // RY /s
#pragma unroll
    for (int j = 0; j < 16; j++) {
      float px = __shfl_xor_sync(0xffffffffu, a[j].x, 1 << LB);
      float py = __shfl_xor_sync(0xffffffffu, a[j].y, 1 << LB);
      a[j].x = fmaf(t, a[j].x, cb ? px : -px);
      a[j].y = fmaf(t, a[j].y, cb ? py : -py);
    }
  } else if (tf == 4) {   // RZ /c: diagonal, no shfl
    const float tt = cb ? -t : t;
#pragma unroll
    for (int j = 0; j < 16; j++) {
      float nx = fmaf( tt, a[j].y, a[j].x);
      float ny = fmaf(-tt, a[j].x, a[j].y);
      a[j].x = nx; a[j].y = ny;
    }
  } else {                // RZ /s: diagonal, no shfl
#pragma unroll
    for (int j = 0; j < 16; j++) {
      float nx = fmaf(t, a[j].x, cb ? -a[j].y : a[j].y);
      float ny = fmaf(t, a[j].y, cb ?  a[j].x : -a[j].x);
      a[j].x = nx; a[j].y = ny;
    }
  }
}

template<int BC, int BT>
__device__ __forceinline__ void cnotl16(float2* a) {
#pragma unroll
  for (int j = 0; j < 16; j++) {
    if (((j >> BC) & 1) == 1 && ((j >> BT) & 1) == 0) {
      int k = j | (1 << BT);
      float2 t = a[j]; a[j] = a[k]; a[k] = t;
    }
  }
}

// Generic factored pair rotation: m = value with qubit label lbl, o = partner
// (label lbl^1); returns new value at label lbl.
__device__ __forceinline__ float2 rotp(float2 m, float2 o, float t,
                                       int f, int lbl) {
  float2 r;
  if (f == 0) {        // RX /c
    r.x = fmaf( t, o.y, m.x);  r.y = fmaf(-t, o.x, m.y);
  } else if (f == 1) { // RX /s
    r.x = fmaf(t, m.x,  o.y);  r.y = fmaf(t, m.y, -o.x);
  } else if (f == 2) { // RY /c
    float sg = lbl ? t : -t;
    r.x = fmaf(sg, o.x, m.x);  r.y = fmaf(sg, o.y, m.y);
  } else {             // RY /s
    r.x = fmaf(t, m.x, lbl ? o.x : -o.x);
    r.y = fmaf(t, m.y, lbl ? o.y : -o.y);
  }
  return r;
}

__device__ __forceinline__ float2 rotd(float2 m, float t, int f, int lbl) {
  float2 r;
  if (f == 4) {        // RZ /c
    float tt = lbl ? -t : t;
    r.x = fmaf( tt, m.y, m.x);  r.y = fmaf(-tt, m.x, m.y);
  } else {             // RZ /s
    r.x = fmaf(t, m.x, lbl ? -m.y : m.y);
    r.y = fmaf(t, m.y, lbl ?  m.x : -m.x);
  }
  return r;
}

// Local amp index i: 14 bits; local bit k <-> qubit (14 - k) (qubits 1..14).
// Qubit 0 <-> cluster rank. Class = (q0 label, q1 label).
__global__ void __launch_bounds__(NTHREADS, 1) __cluster_dims__(2, 1, 1)
qdarts_kernel(const float* __restrict__ x, const float* __restrict__ Pm,
              const float* __restrict__ Qm, const float* __restrict__ rotp_,
              const float* __restrict__ gum, float* __restrict__ out)
{
  extern __shared__ float2 SM[];   // NLOC float2, LINEAR layout

  __shared__ float st_t[N_LAYERS * N_QUBITS];
  __shared__ int   st_f[N_LAYERS * N_QUBITS];
  __shared__ float st_s[N_LAYERS * N_QUBITS];
  __shared__ float sw[N_QUBITS][2];
  __shared__ float sred[4];
  __shared__ float sS2;

  cg::cluster_group cluster = cg::this_cluster();
  const int tid  = threadIdx.x;
  const int b    = blockIdx.x >> 1;
  const int rank = blockIdx.x & 1;
  const int lane = tid & 31;

  // ---- Gate selection: argmax(P@Q + gumbel); store (t, variant, scale). ----
  if (tid < N_LAYERS * N_QUBITS) {
    const int ix = tid;
    float best = -1e30f; int gb = 0;
#pragma unroll
    for (int gg = 0; gg < 3; gg++) {
      float logit = 0.f;
#pragma unroll
      for (int k = 0; k < 4; k++)
        logit += Pm[ix * 4 + k] * Qm[(ix * 4 + k) * 3 + gg];
      float v = logit + gum[ix * 3 + gg];
      if (v > best) { best = v; gb = gg; }
    }
    float sv, cv;
    sincosf(0.5f * rotp_[ix], &sv, &cv);
    const bool formB = fabsf(sv) > fabsf(cv);
    st_f[ix] = gb * 2 + (formB ? 1 : 0);
    st_t[ix] = formB ? __fdividef(cv, sv) : __fdividef(sv, cv);
    st_s[ix] = formB ? sv : cv;
  }
  if (tid < N_QUBITS) {
    float sv, cv;
    sincosf(0.5f * x[b * N_QUBITS + tid], &sv, &cv);
    sw[tid][0] = cv; sw[tid][1] = sv;
  }
  if (tid < 4) sred[tid] = 0.f;
  __syncthreads();

  if (tid == 0) {
    float pr = 1.f;
#pragma unroll 1
    for (int i = 0; i < N_LAYERS * N_QUBITS; i++) pr *= st_s[i];
    sS2 = pr * pr;
  }

  // ---- Sweep A indexing: amp = (tb13<<13)|(j<<10)|(tmid<<1)|p ----
  // reg bits: j = {q2,q3,q4} (amp 12..10), p = q14 (amp 0); a-idx = (j<<1)|p.
  const int tb13 = (tid >> 9) & 1;       // amp bit13 = q1 label
  const int tmid = tid & 511;            // amp bits 9..1
  const int xA   = ((tb13 << 13) | (tmid << 1)) >> 1;   // float4 base index

  // ---- Sweep B indexing: amp = (wHi<<10)|(jb<<6)|(wLo<<5)|lane ----
  // reg jb = {q5..q8} (amp 9..6); wLo = q9 label (amp 5); lane = q10..q14.
  const int wHi = tid >> 6;
  const int wLo = (tid >> 5) & 1;
  const int baseB = (wHi << 10) | (wLo << 5) | lane;

  // Store-perm cascade for CNOT chain (10,11)(11,12)(12,13)(13,14) on lane.
  int u_ = lane;
  u_ ^= (u_ >> 1) & 8;
  u_ ^= (u_ >> 1) & 4;
  u_ ^= (u_ >> 1) & 2;
  u_ ^= (u_ >> 1) & 1;
  const int dstE = u_;
  const int e0 = dstE & 1;

  float pA = 0.f, pB = 0.f;

#pragma unroll 1
  for (int l = 0; l < N_LAYERS; l++) {
    const int g0 = l * N_QUBITS;
    float2 a[16];

    // ======== Sweep A: rotations q0,q1 (pair-on-load), q2..q4, q14 ========
    {
      const float t0 = st_t[g0];     const int f0 = st_f[g0];
      const float t1 = st_t[g0 + 1]; const int f1 = st_f[g0 + 1];
      const bool q0d = (f0 >= 4), q1d = (f1 >= 4);

      if (l == 0) {
        // Analytic product state; q0/q1 chain reduces to one complex z.
        float prefT = 1.f;
#pragma unroll
        for (int q = 5; q <= 13; q++)
          prefT *= sw[q][(tmid >> (13 - q)) & 1];
        float2 q1v;
        {
          float2 m1 = make_float2(sw[1][tb13], 0.f);
          float2 o1 = make_float2(sw[1][tb13 ^ 1], 0.f);
          q1v = q1d ? rotd(m1, t1, f1, tb13) : rotp(m1, o1, t1, f1, tb13);
        }
        float2 zm = make_float2(q1v.x * sw[0][rank], q1v.y * sw[0][rank]);
        float2 zo = make_float2(q1v.x * sw[0][rank ^ 1], q1v.y * sw[0][rank ^ 1]);
        float2 z = q0d ? rotd(zm, t0, f0, rank) : rotp(zm, zo, t0, f0, rank);
        const float w140 = sw[14][0], w141 = sw[14][1];
#pragma unroll
        for (int j = 0; j < 8; j++) {
          float fj = prefT * sw[2][(j >> 2) & 1] * sw[3][(j >> 1) & 1]
                           * sw[4][j & 1];
          float s0 = fj * w140, s1 = fj * w141;
          a[2 * j]     = make_float2(z.x * s0, z.y * s0);
          a[2 * j + 1] = make_float2(z.x * s1, z.y * s1);
        }
      } else {
        const float4* SM4 = (const float4*)SM;
        const float4* PG4 = g_xchg4 + ((size_t)(b * 2 + ((l - 1) & 1)) * 2
                                       + (rank ^ 1)) * (NLOC / 2);
        // p=0 amps: own chain = my SMEM; p=1 amps: own chain = partner
        // (fused CNOT(14,0) role swap — compile-time by p).
#pragma unroll
        for (int j = 0; j < 8; j++) {
          const int xx = xA | (j << 9);
          float4 s0v = SM4[xx];
          float4 g0v = __ldcg(&PG4[xx]);
          float2 sA0 = make_float2(s0v.x, s0v.y), sA1 = make_float2(s0v.z, s0v.w);
          float2 gA0 = make_float2(g0v.x, g0v.y), gA1 = make_float2(g0v.z, g0v.w);
          float2 mO0, mO1, mP0, mP1;
          if (q1d) {
            mO0 = rotd(sA0, t1, f1, tb13);  mO1 = rotd(sA1, t1, f1, tb13);
            mP0 = rotd(gA0, t1, f1, tb13);  mP1 = rotd(gA1, t1, f1, tb13);
          } else {
            float4 s1v = SM4[xx ^ 4096];
            float4 g1v = __ldcg(&PG4[xx ^ 4096]);
            float2 sB0 = make_float2(s1v.x, s1v.y), sB1 = make_float2(s1v.z, s1v.w);
            float2 gB0 = make_float2(g1v.x, g1v.y), gB1 = make_float2(g1v.z, g1v.w);
            mO0 = rotp(sA0, sB0, t1, f1, tb13);
            mO1 = rotp(sA1, sB1, t1, f1, tb13);
            mP0 = rotp(gA0, gB0, t1, f1, tb13);
            mP1 = rotp(gA1, gB1, t1, f1, tb13);
          }
          if (q0d) {
            a[2 * j]     = rotd(mO0, t0, f0, rank);
            a[2 * j + 1] = rotd(mP1, t0, f0, rank);
          } else {
            a[2 * j]     = rotp(mO0, mP0, t0, f0, rank);
            a[2 * j + 1] = rotp(mP1, mO1, t0, f0, rank);
          }
        }
      }
      // Rotations q2 (a bit3), q3 (bit2), q4 (bit1), q14 (bit0 = p).
      rotfac16<3>(a, st_t[g0 + 2],  st_f[g0 + 2]);
      rotfac16<2>(a, st_t[g0 + 3],  st_f[g0 + 3]);
      rotfac16<1>(a, st_t[g0 + 4],  st_f[g0 + 4]);
      rotfac16<0>(a, st_t[g0 + 14], st_f[g0 + 14]);
      // CNOT(1,2): ctrl = q1 post-CNOT(0,1) = tb13^rank (warp-uniform branch);
      // tgt q2 = a bit3.  (Conjugated control compensates for C01 at store.)
      if ((tb13 ^ rank) != 0) {
#pragma unroll
        for (int j2 = 0; j2 < 8; j2++) {
          float2 t2 = a[j2]; a[j2] = a[j2 | 8]; a[j2 | 8] = t2;
        }
      }
      cnotl16<3, 2>(a);  // CNOT(2,3)
      cnotl16<2, 1>(a);  // CNOT(3,4)
      // Store with fold: CNOT(0,1) -> addr ^ (rank<<13).
      // NOTE: CNOT(4,5) is NOT folded here — its target q5's rotation runs
      // in sweep B; the CNOT is applied there AFTER R_q5 (ring order).
      float4* SM4w = (float4*)SM;
      const int xS = xA ^ (rank << 12);
#pragma unroll
      for (int j = 0; j < 8; j++) {
        SM4w[xS | (j << 9)] =
            make_float4(a[2 * j].x, a[2 * j].y, a[2 * j + 1].x, a[2 * j + 1].y);
      }
    }
    __syncthreads();

    // ======== Sweep B: rotations q9 (pair-on-load), q5..q8, q10..q13 ========
    {
      const float t9 = st_t[g0 + 9]; const int f9 = st_f[g0 + 9];
      if (f9 >= 4) {
#pragma unroll
        for (int jb = 0; jb < 16; jb++)
          a[jb] = rotd(SM[baseB | (jb << 6)], t9, f9, wLo);
      } else {
#pragma unroll
        for (int jb = 0; jb < 16; jb++) {
          float2 own = SM[baseB | (jb << 6)];
          float2 par = SM[(baseB ^ 32) | (jb << 6)];
          a[jb] = rotp(own, par, t9, f9, wLo);
        }
      }
      // Rotations q5 (jb bit3), q6 (bit2), q7 (bit1), q8 (bit0).
      rotfac16<3>(a, st_t[g0 + 5], st_f[g0 + 5]);
      rotfac16<2>(a, st_t[g0 + 6], st_f[g0 + 6]);
      rotfac16<1>(a, st_t[g0 + 7], st_f[g0 + 7]);
      rotfac16<0>(a, st_t[g0 + 8], st_f[g0 + 8]);
      // Rotations q10..q13 (lane bits 4..1).  (q14 handled in sweep A.)
      rot_lane_fac16<4>(a, st_t[g0 + 10], st_f[g0 + 10], lane);
      rot_lane_fac16<3>(a, st_t[g0 + 11], st_f[g0 + 11], lane);
      rot_lane_fac16<2>(a, st_t[g0 + 12], st_f[g0 + 12], lane);
      rot_lane_fac16<1>(a, st_t[g0 + 13], st_f[g0 + 13], lane);
      // CNOT(4,5): ctrl q4 = amp bit10 = wHi bit0 = tid bit6 (warp-uniform
      // branch); tgt q5 = jb bit3. Applied AFTER R_q5 — ring order correct.
      if (wHi & 1) {
#pragma unroll
        for (int j2 = 0; j2 < 8; j2++) {
          float2 t2 = a[j2]; a[j2] = a[j2 | 8]; a[j2 | 8] = t2;
        }
      }
      cnotl16<3, 2>(a);  // CNOT(5,6)
      cnotl16<2, 1>(a);  // CNOT(6,7)
      cnotl16<1, 0>(a);  // CNOT(7,8)
      // CNOT(8,9): addr bit5 = wLo ^ (jb&1).
      // CNOT(9,10): cascade pre-flip by ctrl = wLo ^ (jb&1) -> dst ^ 31.
      // CNOT(10,11)..(13,14): cascade (dstE).
      // CNOT(14,0): physical, fused in next sweep-A load roles / reduction.

      if (l < N_LAYERS - 1) {
        float2* xw = (float2*)(g_xchg4
                       + ((size_t)(b * 2 + (l & 1)) * 2 + rank) * (NLOC / 2));
#pragma unroll
        for (int jb = 0; jb < 16; jb++) {
          const int c = wLo ^ (jb & 1);
          const int i = (wHi << 10) | (jb << 6) | (c << 5)
                        | (dstE ^ (c ? 31 : 0));
          SM[i] = a[jb];
          xw[i] = a[jb];
        }
        cluster.sync();
      } else {
        // |amp|^2 class reduction. Final q14 of reg jb = e0 ^ wLo ^ (jb&1);
        // q0 label flips (rank -> rank^1) when q14 = 1; q1 = tb13 (uniform).
        float pe = 0.f, po = 0.f;
#pragma unroll
        for (int jb = 0; jb < 16; jb++) {
          float p = fmaf(a[jb].x, a[jb].x, a[jb].y * a[jb].y);
          if (jb & 1) po += p; else pe += p;
        }
        const int g = e0 ^ wLo;    // q14 of even-jb amps
        pA = g ? po : pe;          // q0 label = rank
        pB = g ? pe : po;          // q0 label = rank^1
      }
    }
  }

  // ---- Reduce: full warp reduce (class meaning lane-uniform) -> CTA -> out --
#pragma unroll
  for (int o = 16; o > 0; o >>= 1) {
    pA += __shfl_xor_sync(0xffffffffu, pA, o);
    pB += __shfl_xor_sync(0xffffffffu, pB, o);
  }
  if (lane == 0) {
    atomicAdd(&sred[(rank << 1) | tb13], pA);
    atomicAdd(&sred[((rank ^ 1) << 1) | tb13], pB);
  }
  __syncthreads();

  if (rank == 1 && tid < 4) {
    float* dst = cluster.map_shared_rank(sred, 0);
    atomicAdd(dst + tid, sred[tid]);
  }
  cluster.sync();
  if (rank == 0 && tid < 4) out[b * 4 + tid] = sred[tid] * sS2;
}

extern "C" void kernel_launch(void* const* d_in, const int* in_sizes, int n_in,
                              void* d_out, int out_size) {
  const float* x    = (const float*)d_in[0];
  const float* P    = (const float*)d_in[1];
  const float* Q    = (const float*)d_in[2];
  const float* rotp = (const float*)d_in[3];
  const float* gum  = (const float*)d_in[4];
  cudaFuncSetAttribute(qdarts_kernel,
                       cudaFuncAttributeMaxDynamicSharedMemorySize,
                       (int)SMEM_BYTES);
  qdarts_kernel<<<BATCHN * 2, NTHREADS, SMEM_BYTES>>>(x, P, Q, rotp, gum,
                                                      (float*)d_out);
}